// round 10
// baseline (speedup 1.0000x reference)
#include <cuda_runtime.h>
#include <cstdint>

#define N_NODES 50000
#define E_EDGES 800000
#define IN_C 10
#define XS_STRIDE 12
#define HID 96
#define OUT_C 48

#define SCAN_T 1024
#define SCAN_CHUNK 49   // ceil(50000/1024)

// Scratch (device globals — no allocation allowed in kernel_launch)
__device__ int   g_deg[N_NODES];
__device__ int   g_fill[N_NODES];
__device__ int   g_ptr[N_NODES + 1];
__device__ int   g_srow[E_EDGES];                   // row indices bucketed by col
__device__ float g_dis[N_NODES];                    // rsqrt(deg+1)
__device__ float g_xs[N_NODES * XS_STRIDE];         // x * dis   (pre-scaled)
__device__ float g_aggx[N_NODES * XS_STRIDE];
__device__ float g_hs[N_NODES * HID];               // relu(aggx@W1+b1) * dis
__device__ float g_aggh[N_NODES * HID];

// --- K0: zero degree + fill counters (graph replays re-run everything) ---
__global__ void k0_zero() {
    int i = blockIdx.x * blockDim.x + threadIdx.x;
    if (i < N_NODES) { g_deg[i] = 0; g_fill[i] = 0; }
}

// --- K1: in-degree histogram over col ---
__global__ void k1_degree(const int* __restrict__ ei) {
    int e = blockIdx.x * blockDim.x + threadIdx.x;
    if (e < E_EDGES) atomicAdd(&g_deg[ei[E_EDGES + e]], 1);
}

// --- K2: exclusive prefix sum of deg -> g_ptr; also dis = rsqrt(deg+1) ---
__global__ void k2_scan() {
    __shared__ int wsum[32];
    int t = threadIdx.x;
    int base = t * SCAN_CHUNK;
    int s = 0;
    for (int k = 0; k < SCAN_CHUNK; k++) {
        int i = base + k;
        if (i < N_NODES) s += g_deg[i];
    }
    int lane = t & 31, w = t >> 5;
    int v = s;
    #pragma unroll
    for (int o = 1; o < 32; o <<= 1) {
        int u = __shfl_up_sync(~0u, v, o);
        if (lane >= o) v += u;
    }
    if (lane == 31) wsum[w] = v;
    __syncthreads();
    if (w == 0) {
        int z = wsum[lane];
        #pragma unroll
        for (int o = 1; o < 32; o <<= 1) {
            int u = __shfl_up_sync(~0u, z, o);
            if (lane >= o) z += u;
        }
        wsum[lane] = z;
    }
    __syncthreads();
    int excl = v - s + ((w > 0) ? wsum[w - 1] : 0);
    int run = excl;
    for (int k = 0; k < SCAN_CHUNK; k++) {
        int i = base + k;
        if (i < N_NODES) {
            int d = g_deg[i];
            g_ptr[i] = run;
            g_dis[i] = rsqrtf((float)d + 1.0f);
            run += d;
        }
    }
    if (t == SCAN_T - 1) g_ptr[N_NODES] = run;
}

// --- K3: xs = x * dis (pre-scaled source features, padded stride) ---
__global__ void k3_xs(const float* __restrict__ x) {
    int i = blockIdx.x * blockDim.x + threadIdx.x;
    if (i < N_NODES * IN_C) {
        int n = i / IN_C, f = i % IN_C;
        g_xs[n * XS_STRIDE + f] = x[i] * g_dis[n];
    }
}

// --- K4: bucket-fill rows by destination col ---
__global__ void k4_fill(const int* __restrict__ ei) {
    int e = blockIdx.x * blockDim.x + threadIdx.x;
    if (e < E_EDGES) {
        int r = ei[e];
        int c = ei[E_EDGES + e];
        int p = atomicAdd(&g_fill[c], 1);
        g_srow[g_ptr[c] + p] = r;
    }
}

// --- K5: pull-mode aggregation of xs (16 threads/node, f<10 active, 4x unroll) ---
__global__ void k5_aggx() {
    int tid = blockIdx.x * blockDim.x + threadIdx.x;
    int n = tid >> 4;
    int f = tid & 15;
    if (n >= N_NODES || f >= IN_C) return;
    float dn = g_dis[n];
    int j = g_ptr[n], end = g_ptr[n + 1];
    float acc0 = g_xs[(size_t)n * XS_STRIDE + f];   // self-loop term xs[n]
    float acc1 = 0.0f, acc2 = 0.0f, acc3 = 0.0f;
    for (; j + 4 <= end; j += 4) {
        int r0 = g_srow[j], r1 = g_srow[j + 1], r2 = g_srow[j + 2], r3 = g_srow[j + 3];
        acc0 += g_xs[(size_t)r0 * XS_STRIDE + f];
        acc1 += g_xs[(size_t)r1 * XS_STRIDE + f];
        acc2 += g_xs[(size_t)r2 * XS_STRIDE + f];
        acc3 += g_xs[(size_t)r3 * XS_STRIDE + f];
    }
    for (; j < end; j++)
        acc0 += g_xs[(size_t)g_srow[j] * XS_STRIDE + f];
    g_aggx[(size_t)n * XS_STRIDE + f] = dn * ((acc0 + acc1) + (acc2 + acc3));
}

// --- K6: hs = relu(aggx @ W1 + b1) * dis ---
__global__ void k6_hidden(const float* __restrict__ W1, const float* __restrict__ b1) {
    __shared__ float sW[IN_C * HID];
    for (int t = threadIdx.x; t < IN_C * HID; t += blockDim.x) sW[t] = W1[t];
    __syncthreads();
    int idx = blockIdx.x * blockDim.x + threadIdx.x;
    if (idx < N_NODES * HID) {
        int n = idx / HID, f = idx % HID;
        float s = b1[f];
        const float* ax = g_aggx + (size_t)n * XS_STRIDE;
        #pragma unroll
        for (int i = 0; i < IN_C; i++)
            s = fmaf(ax[i], sW[i * HID + f], s);
        g_hs[idx] = fmaxf(s, 0.0f) * g_dis[n];
    }
}

// --- K7: pull-mode aggregation of hs (warp/node, 3 feats/lane, 4x unroll) ---
// aggh[n] = dis[n] * (sum_r hs[r] + hs[n]); pure gather+add, MLP=12.
__global__ void k7_aggh() {
    int n = (blockIdx.x * blockDim.x + threadIdx.x) >> 5;
    int lane = threadIdx.x & 31;
    if (n >= N_NODES) return;
    float dn = g_dis[n];
    int j = g_ptr[n], end = g_ptr[n + 1];
    const float* hn = g_hs + (size_t)n * HID;
    float a0 = hn[lane], a1 = hn[32 + lane], a2 = hn[64 + lane];  // self-loop
    float b0 = 0.f, b1 = 0.f, b2 = 0.f;
    for (; j + 4 <= end; j += 4) {
        int r0 = g_srow[j], r1 = g_srow[j + 1], r2 = g_srow[j + 2], r3 = g_srow[j + 3];
        const float* h0 = g_hs + (size_t)r0 * HID;
        const float* h1 = g_hs + (size_t)r1 * HID;
        const float* h2 = g_hs + (size_t)r2 * HID;
        const float* h3 = g_hs + (size_t)r3 * HID;
        float v00 = h0[lane], v01 = h0[32 + lane], v02 = h0[64 + lane];
        float v10 = h1[lane], v11 = h1[32 + lane], v12 = h1[64 + lane];
        float v20 = h2[lane], v21 = h2[32 + lane], v22 = h2[64 + lane];
        float v30 = h3[lane], v31 = h3[32 + lane], v32 = h3[64 + lane];
        a0 += v00 + v10; b0 += v20 + v30;
        a1 += v01 + v11; b1 += v21 + v31;
        a2 += v02 + v12; b2 += v22 + v32;
    }
    for (; j < end; j++) {
        const float* hr = g_hs + (size_t)g_srow[j] * HID;
        a0 += hr[lane]; a1 += hr[32 + lane]; a2 += hr[64 + lane];
    }
    float* an = g_aggh + (size_t)n * HID;
    an[lane]      = dn * (a0 + b0);
    an[32 + lane] = dn * (a1 + b1);
    an[64 + lane] = dn * (a2 + b2);
}

// --- K8: mu/logstd = aggh @ {Wmu|Wls} + bias, 8-node register blocking ---
__global__ void k8_out(const float* __restrict__ Wmu, const float* __restrict__ bmu,
                       const float* __restrict__ Wls, const float* __restrict__ bls,
                       float* __restrict__ out) {
    __shared__ float sW[HID][HID];     // cols [0,48)=Wmu, [48,96)=Wls
    __shared__ float srow[8][HID];
    for (int t = threadIdx.x; t < HID * HID; t += blockDim.x) {
        int i = t / HID, j = t % HID;
        sW[i][j] = (j < OUT_C) ? Wmu[i * OUT_C + j]
                               : Wls[i * OUT_C + (j - OUT_C)];
    }
    __syncthreads();
    int j = threadIdx.x;   // 0..95
    float bias = (j < OUT_C) ? bmu[j] : bls[j - OUT_C];
    for (int n0 = blockIdx.x * 8; n0 < N_NODES; n0 += gridDim.x * 8) {   // 8 | 50000
        #pragma unroll
        for (int k = 0; k < 8; k++)
            srow[k][j] = g_aggh[(size_t)(n0 + k) * HID + j];
        __syncthreads();
        float s[8];
        #pragma unroll
        for (int k = 0; k < 8; k++) s[k] = bias;
        #pragma unroll
        for (int i = 0; i < HID; i++) {
            float w = sW[i][j];
            #pragma unroll
            for (int k = 0; k < 8; k++)
                s[k] = fmaf(srow[k][i], w, s[k]);
        }
        size_t half = (size_t)N_NODES * OUT_C;
        if (j < OUT_C) {
            #pragma unroll
            for (int k = 0; k < 8; k++)
                out[(size_t)(n0 + k) * OUT_C + j] = s[k];
        } else {
            int jj = j - OUT_C;
            #pragma unroll
            for (int k = 0; k < 8; k++)
                out[half + (size_t)(n0 + k) * OUT_C + jj] = s[k];
        }
        __syncthreads();
    }
}

extern "C" void kernel_launch(void* const* d_in, const int* in_sizes, int n_in,
                              void* d_out, int out_size) {
    const float* x   = (const float*)d_in[0];
    const int*   ei  = (const int*)d_in[1];
    const float* W1  = (const float*)d_in[2];
    const float* b1  = (const float*)d_in[3];
    const float* Wmu = (const float*)d_in[4];
    const float* bmu = (const float*)d_in[5];
    const float* Wls = (const float*)d_in[6];
    const float* bls = (const float*)d_in[7];
    float* out = (float*)d_out;

    k0_zero<<<(N_NODES + 255) / 256, 256>>>();
    k1_degree<<<(E_EDGES + 255) / 256, 256>>>(ei);
    k2_scan<<<1, SCAN_T>>>();
    k3_xs<<<(N_NODES * IN_C + 255) / 256, 256>>>(x);
    k4_fill<<<(E_EDGES + 255) / 256, 256>>>(ei);
    k5_aggx<<<(N_NODES * 16 + 255) / 256, 256>>>();
    k6_hidden<<<(N_NODES * HID + 255) / 256, 256>>>(W1, b1);
    k7_aggh<<<(N_NODES * 32 + 255) / 256, 256>>>();
    k8_out<<<1024, HID>>>(Wmu, bmu, Wls, bls, out);
}

// round 11
// speedup vs baseline: 1.7670x; 1.7670x over previous
#include <cuda_runtime.h>
#include <cuda_fp16.h>
#include <cstdint>

#define N_NODES 50000
#define E_EDGES 800000
#define IN_C 10
#define XS_STRIDE 12
#define HID 96
#define H2_STRIDE 64     // half2 per hs row: 48 real + 16 zero-pad -> 256B stride
#define OUT_C 48
#define NBLK 196         // ceil(50000/256)

// Scratch (device globals — no allocation allowed in kernel_launch)
__device__ int   g_deg[N_NODES];
__device__ int   g_fill[N_NODES];
__device__ int   g_ptr[N_NODES + 1];
__device__ int   g_bsum[NBLK];
__device__ int   g_boff[NBLK];
__device__ int   g_srow[E_EDGES];
__device__ float g_dis[N_NODES];
__device__ __align__(16) float   g_xs[N_NODES * XS_STRIDE];
__device__ __align__(16) float   g_aggx[N_NODES * XS_STRIDE];
__device__ __align__(16) __half2 g_hs2[N_NODES * H2_STRIDE];
__device__ __align__(16) float   g_aggh[N_NODES * HID];

// ---- packed f32x2 helpers (sm_103a FFMA2) ----
__device__ __forceinline__ unsigned long long pack2(float x, float y) {
    unsigned long long r;
    asm("mov.b64 %0, {%1,%2};" : "=l"(r) : "f"(x), "f"(y));
    return r;
}
__device__ __forceinline__ void unpack2(unsigned long long v, float& x, float& y) {
    asm("mov.b64 {%0,%1}, %2;" : "=f"(x), "=f"(y) : "l"(v));
}
__device__ __forceinline__ void fma2(unsigned long long& d, unsigned long long a,
                                     unsigned long long b) {
    asm("fma.rn.f32x2 %0, %1, %2, %0;" : "+l"(d) : "l"(a), "l"(b));
}

// ---- block-wide exclusive scan over 256 threads ----
__device__ __forceinline__ int block_excl_scan_256(int v, int* wsum) {
    int lane = threadIdx.x & 31, w = threadIdx.x >> 5;
    int inc = v;
    #pragma unroll
    for (int o = 1; o < 32; o <<= 1) {
        int u = __shfl_up_sync(~0u, inc, o);
        if (lane >= o) inc += u;
    }
    if (lane == 31) wsum[w] = inc;
    __syncthreads();
    if (threadIdx.x < 8) {
        int z = wsum[threadIdx.x];
        #pragma unroll
        for (int o = 1; o < 8; o <<= 1) {
            int u = __shfl_up_sync(0xffu, z, o);
            if ((int)threadIdx.x >= o) z += u;
        }
        wsum[threadIdx.x] = z;
    }
    __syncthreads();
    int off = (w > 0) ? wsum[w - 1] : 0;
    return off + inc - v;
}

// --- K0: zero degree counters ---
__global__ void k0_zero() {
    int i = blockIdx.x * blockDim.x + threadIdx.x;
    if (i < N_NODES) g_deg[i] = 0;
}

// --- K1: in-degree histogram over col ---
__global__ void k1_degree(const int* __restrict__ ei) {
    int e = blockIdx.x * blockDim.x + threadIdx.x;
    if (e < E_EDGES) atomicAdd(&g_deg[ei[E_EDGES + e]], 1);
}

// --- KA: per-block degree sums ---
__global__ void kA_bsum() {
    int i = blockIdx.x * 256 + threadIdx.x;
    int d = (i < N_NODES) ? g_deg[i] : 0;
    #pragma unroll
    for (int o = 16; o > 0; o >>= 1) d += __shfl_down_sync(~0u, d, o);
    __shared__ int ws[8];
    if ((threadIdx.x & 31) == 0) ws[threadIdx.x >> 5] = d;
    __syncthreads();
    if (threadIdx.x == 0) {
        int s = 0;
        #pragma unroll
        for (int k = 0; k < 8; k++) s += ws[k];
        g_bsum[blockIdx.x] = s;
    }
}

// --- KB: exclusive scan of block sums (one block) ---
__global__ void kB_scanb() {
    __shared__ int ws[8];
    int t = threadIdx.x;
    int v = (t < NBLK) ? g_bsum[t] : 0;
    int excl = block_excl_scan_256(v, ws);
    if (t < NBLK) g_boff[t] = excl;
}

// --- KC: ptr = boff + in-block scan; dis; xs = x*dis; fill = 0 ---
__global__ void kC_apply(const float* __restrict__ x) {
    __shared__ int ws[8];
    int t = threadIdx.x, b = blockIdx.x;
    int i = b * 256 + t;
    int d = (i < N_NODES) ? g_deg[i] : 0;
    int excl = block_excl_scan_256(d, ws);
    if (i < N_NODES) {
        int p = g_boff[b] + excl;
        g_ptr[i] = p;
        g_fill[i] = 0;
        float di = rsqrtf((float)d + 1.0f);
        g_dis[i] = di;
        const float* xi = x + (size_t)i * IN_C;
        float* xo = g_xs + (size_t)i * XS_STRIDE;
        #pragma unroll
        for (int f = 0; f < IN_C; f++) xo[f] = xi[f] * di;
        if (i == N_NODES - 1) g_ptr[N_NODES] = p + d;
    }
}

// --- K4: bucket-fill rows by destination col ---
__global__ void k4_fill(const int* __restrict__ ei) {
    int e = blockIdx.x * blockDim.x + threadIdx.x;
    if (e < E_EDGES) {
        int r = ei[e];
        int c = ei[E_EDGES + e];
        int p = atomicAdd(&g_fill[c], 1);
        g_srow[g_ptr[c] + p] = r;
    }
}

// --- K5: pull-mode aggregation of xs (16 threads/node, f<10 active) ---
__global__ void k5_aggx() {
    int tid = blockIdx.x * blockDim.x + threadIdx.x;
    int n = tid >> 4;
    int f = tid & 15;
    if (n >= N_NODES || f >= IN_C) return;
    float dn = g_dis[n];
    int j = g_ptr[n], end = g_ptr[n + 1];
    float acc = g_xs[(size_t)n * XS_STRIDE + f];   // self-loop term
    #pragma unroll 4
    for (; j < end; j++)
        acc += g_xs[(size_t)g_srow[j] * XS_STRIDE + f];
    g_aggx[(size_t)n * XS_STRIDE + f] = dn * acc;
}

// --- K6: hs = fp16( relu(aggx @ W1 + b1) * dis ), padded half2 rows ---
// blockDim 256 = 4 nodes x 64 half2-slots. 50000 % 4 == 0.
__global__ void k6_hidden(const float* __restrict__ W1, const float* __restrict__ b1) {
    __shared__ float sW[IN_C * HID];
    __shared__ float sb[HID];
    __shared__ float sax[4][IN_C];
    for (int t = threadIdx.x; t < IN_C * HID; t += blockDim.x) sW[t] = W1[t];
    if (threadIdx.x < HID) sb[threadIdx.x] = b1[threadIdx.x];
    int g = threadIdx.x >> 6;           // node within block
    int k = threadIdx.x & 63;           // half2 slot
    int n = blockIdx.x * 4 + g;
    if (k < IN_C) sax[g][k] = g_aggx[(size_t)n * XS_STRIDE + k];
    __syncthreads();
    __half2 outv = __floats2half2_rn(0.0f, 0.0f);
    if (k < 48) {
        int f0 = 2 * k;
        float s0 = sb[f0], s1 = sb[f0 + 1];
        #pragma unroll
        for (int i = 0; i < IN_C; i++) {
            float a = sax[g][i];
            s0 = fmaf(a, sW[i * HID + f0],     s0);
            s1 = fmaf(a, sW[i * HID + f0 + 1], s1);
        }
        float dn = g_dis[n];
        outv = __floats2half2_rn(fmaxf(s0, 0.0f) * dn, fmaxf(s1, 0.0f) * dn);
    }
    g_hs2[(size_t)n * H2_STRIDE + k] = outv;
}

// --- K7: pull-mode aggregation of hs (warp/node, fp16 gather, fp32 accum) ---
// aggh[n] = dis[n] * (sum_r hs[r] + hs[n])
__global__ void k7_aggh() {
    int n = (blockIdx.x * blockDim.x + threadIdx.x) >> 5;
    int lane = threadIdx.x & 31;
    if (n >= N_NODES) return;
    float dn = g_dis[n];
    int j = g_ptr[n], end = g_ptr[n + 1];
    const __half2* hn = g_hs2 + (size_t)n * H2_STRIDE;
    float2 u = __half22float2(hn[lane]);
    float2 v = __half22float2(hn[32 + lane]);
    float a0 = u.x, a1 = u.y, a2 = v.x, a3 = v.y;    // self-loop
    #pragma unroll 4
    for (; j < end; j++) {
        const __half2* hr = g_hs2 + (size_t)g_srow[j] * H2_STRIDE;
        float2 p = __half22float2(hr[lane]);
        float2 q = __half22float2(hr[32 + lane]);
        a0 += p.x; a1 += p.y; a2 += q.x; a3 += q.y;
    }
    float* an = g_aggh + (size_t)n * HID;
    ((float2*)an)[lane] = make_float2(dn * a0, dn * a1);          // feats 0..63
    if (lane < 16)
        ((float2*)(an + 64))[lane] = make_float2(dn * a2, dn * a3); // feats 64..95
}

// --- K8: mu/logstd GEMM with packed FFMA2 (node pairs in 8B smem words) ---
// blockDim 192 = 4 groups x 48 cols; each group handles 8 nodes (4 pairs).
__global__ void __launch_bounds__(192) k8_out(
        const float* __restrict__ Wmu, const float* __restrict__ bmu,
        const float* __restrict__ Wls, const float* __restrict__ bls,
        float* __restrict__ out) {
    __shared__ float sW[HID * HID];                        // 36864 B
    __shared__ unsigned long long srw[4][HID][4];          // 12288 B (total 48 KB)
    int tid = threadIdx.x;
    for (int t = tid; t < HID * HID; t += 192) {
        int i = t / HID, j = t % HID;
        sW[t] = (j < OUT_C) ? Wmu[i * OUT_C + j] : Wls[i * OUT_C + (j - OUT_C)];
    }
    int g = tid / 48, j = tid % 48;
    int n0 = blockIdx.x * 32 + g * 8;
    for (int idx = j; idx < 8 * HID; idx += 48) {
        int k = idx / HID, c = idx % HID;
        int n = n0 + k;
        float val = (n < N_NODES) ? g_aggh[(size_t)n * HID + c] : 0.0f;
        ((float*)&srw[g][c][k >> 1])[k & 1] = val;
    }
    __syncthreads();
    unsigned long long acc[8];
    {
        float bm = bmu[j], bl = bls[j];
        #pragma unroll
        for (int p = 0; p < 4; p++) { acc[p] = pack2(bm, bm); acc[4 + p] = pack2(bl, bl); }
    }
    #pragma unroll 8
    for (int i = 0; i < HID; i++) {
        float wmu = sW[i * HID + j];
        float wls = sW[i * HID + OUT_C + j];
        unsigned long long w2m = pack2(wmu, wmu);
        unsigned long long w2l = pack2(wls, wls);
        #pragma unroll
        for (int p = 0; p < 4; p++) {
            unsigned long long s = srw[g][i][p];
            fma2(acc[p],     w2m, s);
            fma2(acc[4 + p], w2l, s);
        }
    }
    size_t half = (size_t)N_NODES * OUT_C;
    #pragma unroll
    for (int p = 0; p < 4; p++) {
        int na = n0 + 2 * p, nb = na + 1;
        float x0, x1;
        unpack2(acc[p], x0, x1);
        if (na < N_NODES) out[(size_t)na * OUT_C + j] = x0;
        if (nb < N_NODES) out[(size_t)nb * OUT_C + j] = x1;
        unpack2(acc[4 + p], x0, x1);
        if (na < N_NODES) out[half + (size_t)na * OUT_C + j] = x0;
        if (nb < N_NODES) out[half + (size_t)nb * OUT_C + j] = x1;
    }
}

extern "C" void kernel_launch(void* const* d_in, const int* in_sizes, int n_in,
                              void* d_out, int out_size) {
    const float* x   = (const float*)d_in[0];
    const int*   ei  = (const int*)d_in[1];
    const float* W1  = (const float*)d_in[2];
    const float* b1  = (const float*)d_in[3];
    const float* Wmu = (const float*)d_in[4];
    const float* bmu = (const float*)d_in[5];
    const float* Wls = (const float*)d_in[6];
    const float* bls = (const float*)d_in[7];
    float* out = (float*)d_out;

    k0_zero<<<NBLK, 256>>>();
    k1_degree<<<(E_EDGES + 255) / 256, 256>>>(ei);
    kA_bsum<<<NBLK, 256>>>();
    kB_scanb<<<1, 256>>>();
    kC_apply<<<NBLK, 256>>>(x);
    k4_fill<<<(E_EDGES + 255) / 256, 256>>>(ei);
    k5_aggx<<<(N_NODES * 16 + 255) / 256, 256>>>();
    k6_hidden<<<N_NODES / 4, 256>>>(W1, b1);
    k7_aggh<<<(N_NODES * 32 + 255) / 256, 256>>>();
    k8_out<<<(N_NODES + 31) / 32, 192>>>(Wmu, bmu, Wls, bls, out);
}

// round 12
// speedup vs baseline: 1.8785x; 1.0631x over previous
#include <cuda_runtime.h>
#include <cuda_fp16.h>
#include <cstdint>

#define N_NODES 50000
#define E_EDGES 800000
#define IN_C 10
#define XS_STRIDE 12
#define HID 96
#define OUT_C 48
#define NBLK 196         // ceil(50000/256)

// Scratch (device globals — statically zero-initialized; no runtime alloc)
__device__ int   g_deg[N_NODES];        // re-zeroed by k4 each call (last reader: kC)
__device__ int   g_fill[N_NODES];
__device__ int   g_ptr[N_NODES + 1];
__device__ int   g_bsum[NBLK];
__device__ int   g_srow[E_EDGES];
__device__ float g_dis[N_NODES];
__device__ __align__(16) float   g_xs[N_NODES * XS_STRIDE];
__device__ __align__(16) __half2 g_hsA[N_NODES * 32];   // feature half2 0..31 (128B/row)
__device__ __align__(16) __half2 g_hsB[N_NODES * 16];   // feature half2 32..47 (64B/row)
__device__ __align__(16) float   g_aggh[N_NODES * HID];

// ---- packed f32x2 helpers (sm_103a FFMA2) ----
__device__ __forceinline__ unsigned long long pack2(float x, float y) {
    unsigned long long r;
    asm("mov.b64 %0, {%1,%2};" : "=l"(r) : "f"(x), "f"(y));
    return r;
}
__device__ __forceinline__ void unpack2(unsigned long long v, float& x, float& y) {
    asm("mov.b64 {%0,%1}, %2;" : "=f"(x), "=f"(y) : "l"(v));
}
__device__ __forceinline__ void fma2(unsigned long long& d, unsigned long long a,
                                     unsigned long long b) {
    asm("fma.rn.f32x2 %0, %1, %2, %0;" : "+l"(d) : "l"(a), "l"(b));
}

// ---- block-wide exclusive scan over 256 threads ----
__device__ __forceinline__ int block_excl_scan_256(int v, int* wsum) {
    int lane = threadIdx.x & 31, w = threadIdx.x >> 5;
    int inc = v;
    #pragma unroll
    for (int o = 1; o < 32; o <<= 1) {
        int u = __shfl_up_sync(~0u, inc, o);
        if (lane >= o) inc += u;
    }
    if (lane == 31) wsum[w] = inc;
    __syncthreads();
    if (threadIdx.x < 8) {
        int z = wsum[threadIdx.x];
        #pragma unroll
        for (int o = 1; o < 8; o <<= 1) {
            int u = __shfl_up_sync(0xffu, z, o);
            if ((int)threadIdx.x >= o) z += u;
        }
        wsum[threadIdx.x] = z;
    }
    __syncthreads();
    int off = (w > 0) ? wsum[w - 1] : 0;
    return off + inc - v;
}

// --- K1: in-degree histogram over col (g_deg is zero on entry: static init
//         on the first call, re-zeroed by k4 on every call thereafter) ---
__global__ void k1_degree(const int* __restrict__ ei) {
    int e = blockIdx.x * blockDim.x + threadIdx.x;
    if (e < E_EDGES) atomicAdd(&g_deg[ei[E_EDGES + e]], 1);
}

// --- KA: per-block degree sums ---
__global__ void kA_bsum() {
    int i = blockIdx.x * 256 + threadIdx.x;
    int d = (i < N_NODES) ? g_deg[i] : 0;
    #pragma unroll
    for (int o = 16; o > 0; o >>= 1) d += __shfl_down_sync(~0u, d, o);
    __shared__ int ws[8];
    if ((threadIdx.x & 31) == 0) ws[threadIdx.x >> 5] = d;
    __syncthreads();
    if (threadIdx.x == 0) {
        int s = 0;
        #pragma unroll
        for (int k = 0; k < 8; k++) s += ws[k];
        g_bsum[blockIdx.x] = s;
    }
}

// --- KC: block offset from bsum scan (done per-block) + in-block node scan;
//         ptr, dis, xs = x*dis, fill = 0 ---
__global__ void kC_apply(const float* __restrict__ x) {
    __shared__ int ws[8];
    __shared__ int s_boff;
    int t = threadIdx.x, b = blockIdx.x;
    // scan the 196 block sums; thread b holds this block's exclusive offset
    int bv = (t < NBLK) ? g_bsum[t] : 0;
    int bexcl = block_excl_scan_256(bv, ws);
    if (t == b) s_boff = bexcl;
    __syncthreads();
    // per-node scan within block
    int i = b * 256 + t;
    int d = (i < N_NODES) ? g_deg[i] : 0;
    int excl = block_excl_scan_256(d, ws);
    if (i < N_NODES) {
        int p = s_boff + excl;
        g_ptr[i] = p;
        g_fill[i] = 0;
        float di = rsqrtf((float)d + 1.0f);
        g_dis[i] = di;
        const float* xi = x + (size_t)i * IN_C;
        float* xo = g_xs + (size_t)i * XS_STRIDE;
        #pragma unroll
        for (int f = 0; f < IN_C; f++) xo[f] = xi[f] * di;
        if (i == N_NODES - 1) g_ptr[N_NODES] = p + d;
    }
}

// --- K4: bucket-fill rows by destination col; re-zero g_deg for next call ---
__global__ void k4_fill(const int* __restrict__ ei) {
    int e = blockIdx.x * blockDim.x + threadIdx.x;
    if (e < E_EDGES) {
        int r = ei[e];
        int c = ei[E_EDGES + e];
        int p = atomicAdd(&g_fill[c], 1);
        g_srow[g_ptr[c] + p] = r;
    }
    if (e < N_NODES) g_deg[e] = 0;   // g_deg's last reader was kC
}

// --- K56: fused layer-1 aggregate + project + fp16 store.
// Block = 256 threads = 16 nodes x 16 threads.
// Phase 1: lanes f<10 pull-aggregate xs -> smem. Phase 2: each of the 16
// threads per node computes 3 half2 output columns of hs = relu(.@W1+b1)*dis.
__global__ void k56_hidden(const float* __restrict__ W1, const float* __restrict__ b1) {
    __shared__ float sW[IN_C * HID];
    __shared__ float sb[HID];
    __shared__ float sagg[16][IN_C];
    for (int t = threadIdx.x; t < IN_C * HID; t += 256) sW[t] = W1[t];
    if (threadIdx.x < HID) sb[threadIdx.x] = b1[threadIdx.x];
    int g = threadIdx.x >> 4;        // node within block
    int f = threadIdx.x & 15;
    int n = blockIdx.x * 16 + g;     // 50000 % 16 == 0
    float dn = g_dis[n];
    if (f < IN_C) {
        int j = g_ptr[n], end = g_ptr[n + 1];
        float acc = g_xs[(size_t)n * XS_STRIDE + f];   // self-loop term
        #pragma unroll 4
        for (; j < end; j++)
            acc += g_xs[(size_t)g_srow[j] * XS_STRIDE + f];
        sagg[g][f] = dn * acc;
    }
    __syncthreads();
    float a[IN_C];
    #pragma unroll
    for (int i = 0; i < IN_C; i++) a[i] = sagg[g][i];
    #pragma unroll
    for (int cc = 0; cc < 3; cc++) {
        int c = f + cc * 16;         // half2 column 0..47
        int f0 = 2 * c;
        float s0 = sb[f0], s1 = sb[f0 + 1];
        #pragma unroll
        for (int i = 0; i < IN_C; i++) {
            s0 = fmaf(a[i], sW[i * HID + f0],     s0);
            s1 = fmaf(a[i], sW[i * HID + f0 + 1], s1);
        }
        __half2 hv = __floats2half2_rn(fmaxf(s0, 0.0f) * dn, fmaxf(s1, 0.0f) * dn);
        if (c < 32) g_hsA[(size_t)n * 32 + c] = hv;
        else        g_hsB[(size_t)n * 16 + (c - 32)] = hv;
    }
}

// --- K7: pull-mode aggregation of hs (warp/node, split fp16 rows) ---
// aggh[n] = dis[n] * (sum_r hs[r] + hs[n]); lanes 16-31 idle on the B half.
__global__ void k7_aggh() {
    int n = (blockIdx.x * blockDim.x + threadIdx.x) >> 5;
    int lane = threadIdx.x & 31;
    if (n >= N_NODES) return;
    float dn = g_dis[n];
    int j = g_ptr[n], end = g_ptr[n + 1];
    float2 u = __half22float2(g_hsA[(size_t)n * 32 + lane]);
    float a0 = u.x, a1 = u.y;                      // self-loop
    float a2 = 0.0f, a3 = 0.0f;
    if (lane < 16) {
        float2 v = __half22float2(g_hsB[(size_t)n * 16 + lane]);
        a2 = v.x; a3 = v.y;
    }
    #pragma unroll 4
    for (; j < end; j++) {
        int r = g_srow[j];
        float2 p = __half22float2(g_hsA[(size_t)r * 32 + lane]);
        a0 += p.x; a1 += p.y;
        if (lane < 16) {
            float2 q = __half22float2(g_hsB[(size_t)r * 16 + lane]);
            a2 += q.x; a3 += q.y;
        }
    }
    float* an = g_aggh + (size_t)n * HID;
    ((float2*)an)[lane] = make_float2(dn * a0, dn * a1);            // feats 0..63
    if (lane < 16)
        ((float2*)(an + 64))[lane] = make_float2(dn * a2, dn * a3); // feats 64..95
}

// --- K8: mu/logstd GEMM with packed FFMA2 (node pairs in 8B smem words) ---
// blockDim 192 = 4 groups x 48 cols; each group handles 8 nodes (4 pairs).
__global__ void __launch_bounds__(192) k8_out(
        const float* __restrict__ Wmu, const float* __restrict__ bmu,
        const float* __restrict__ Wls, const float* __restrict__ bls,
        float* __restrict__ out) {
    __shared__ float sW[HID * HID];                        // 36864 B
    __shared__ unsigned long long srw[4][HID][4];          // 12288 B (total 48 KB)
    int tid = threadIdx.x;
    for (int t = tid; t < HID * HID; t += 192) {
        int i = t / HID, j = t % HID;
        sW[t] = (j < OUT_C) ? Wmu[i * OUT_C + j] : Wls[i * OUT_C + (j - OUT_C)];
    }
    int g = tid / 48, j = tid % 48;
    int n0 = blockIdx.x * 32 + g * 8;
    for (int idx = j; idx < 8 * HID; idx += 48) {
        int k = idx / HID, c = idx % HID;
        int n = n0 + k;
        float val = (n < N_NODES) ? g_aggh[(size_t)n * HID + c] : 0.0f;
        ((float*)&srw[g][c][k >> 1])[k & 1] = val;
    }
    __syncthreads();
    unsigned long long acc[8];
    {
        float bm = bmu[j], bl = bls[j];
        #pragma unroll
        for (int p = 0; p < 4; p++) { acc[p] = pack2(bm, bm); acc[4 + p] = pack2(bl, bl); }
    }
    #pragma unroll 8
    for (int i = 0; i < HID; i++) {
        float wmu = sW[i * HID + j];
        float wls = sW[i * HID + OUT_C + j];
        unsigned long long w2m = pack2(wmu, wmu);
        unsigned long long w2l = pack2(wls, wls);
        #pragma unroll
        for (int p = 0; p < 4; p++) {
            unsigned long long s = srw[g][i][p];
            fma2(acc[p],     w2m, s);
            fma2(acc[4 + p], w2l, s);
        }
    }
    size_t half = (size_t)N_NODES * OUT_C;
    #pragma unroll
    for (int p = 0; p < 4; p++) {
        int na = n0 + 2 * p, nb = na + 1;
        float x0, x1;
        unpack2(acc[p], x0, x1);
        if (na < N_NODES) out[(size_t)na * OUT_C + j] = x0;
        if (nb < N_NODES) out[(size_t)nb * OUT_C + j] = x1;
        unpack2(acc[4 + p], x0, x1);
        if (na < N_NODES) out[half + (size_t)na * OUT_C + j] = x0;
        if (nb < N_NODES) out[half + (size_t)nb * OUT_C + j] = x1;
    }
}

extern "C" void kernel_launch(void* const* d_in, const int* in_sizes, int n_in,
                              void* d_out, int out_size) {
    const float* x   = (const float*)d_in[0];
    const int*   ei  = (const int*)d_in[1];
    const float* W1  = (const float*)d_in[2];
    const float* b1  = (const float*)d_in[3];
    const float* Wmu = (const float*)d_in[4];
    const float* bmu = (const float*)d_in[5];
    const float* Wls = (const float*)d_in[6];
    const float* bls = (const float*)d_in[7];
    float* out = (float*)d_out;

    k1_degree<<<(E_EDGES + 255) / 256, 256>>>(ei);
    kA_bsum<<<NBLK, 256>>>();
    kC_apply<<<NBLK, 256>>>(x);
    k4_fill<<<(E_EDGES + 255) / 256, 256>>>(ei);
    k56_hidden<<<N_NODES / 16, 256>>>(W1, b1);
    k7_aggh<<<(N_NODES * 32 + 255) / 256, 256>>>();
    k8_out<<<(N_NODES + 31) / 32, 192>>>(Wmu, bmu, Wls, bls, out);
}